// round 10
// baseline (speedup 1.0000x reference)
#include <cuda_runtime.h>
#include <cstdint>

// out[n,64] = sum over edges e with dst[e]==n of x[src[e],:] * w[e]
// Inputs: x (float32, N*64), edge_index ((2,E), int64-or-int32), edge_weight (float32, E)
//
// Bucketed CSR-lite with self-cleaning state:
//   probe : 1 block — detect index dtype (int64 vs int32)
//   fill  : bucket each edge by dst ({src,w} 8B record); overflow -> list
//   gather: 16 threads/node, atomic-free accumulate, plain STG per row;
//           resets its node's counter for the next replay
//   fixup : 1 block — applies overflow edges (normally zero) and resets tail
// Counters are zero at module load and re-zeroed by gather each execution,
// so no bulk init pass is needed. No output zeroing: gather writes every row.

static constexpr int D    = 64;       // feature dim
static constexpr int TPB  = 256;
static constexpr int MAXN = 100352;   // >= N (problem: 100000)
static constexpr int CAP  = 32;       // bucket slots/node (P(deg>32) ~ 4e-6 overall)
static constexpr int OVFC = 1250000;  // overflow capacity >= E (worst case)

// ---- device scratch (static globals: sanctioned no-alloc scratch) ----
__device__ int g_idx_is64;
__device__ int g_ovf_tail;                                    // zero-init, self-reset
__device__ int g_count[MAXN];                                 // zero-init, self-reset
__device__ unsigned long long g_bucket[(size_t)MAXN * CAP];   // {src, w} records
__device__ unsigned long long g_ovf_rec[OVFC];                // overflow {src, w}
__device__ int g_ovf_dst[OVFC];                               // overflow dst

__device__ __forceinline__ void red_v4(float* p, float4 m) {
    asm volatile("red.global.add.v4.f32 [%0], {%1, %2, %3, %4};"
                 :: "l"(p), "f"(m.x), "f"(m.y), "f"(m.z), "f"(m.w)
                 : "memory");
}

// ---- 1) probe: detect index dtype (1 block) ----
// int64 indices < 2^31 => every odd 32-bit word is zero; int32 indices are
// random node ids, so all-zero over 1024 samples has probability ~1e-5024.
__global__ void probe_kernel(const int* __restrict__ ei32, int E) {
    __shared__ int any_nonzero;
    if (threadIdx.x == 0) any_nonzero = 0;
    __syncthreads();
    int n = E < 1024 ? E : 1024;
    for (int k = threadIdx.x; k < n; k += blockDim.x)
        if (ei32[2 * k + 1] != 0) any_nonzero = 1;
    __syncthreads();
    if (threadIdx.x == 0) g_idx_is64 = (any_nonzero == 0) ? 1 : 0;
}

// ---- 2) fill: bucket every edge by dst (counters arrive zeroed) ----
__global__ __launch_bounds__(TPB)
void fill_kernel(const void* __restrict__ edge_index,
                 const float* __restrict__ w,
                 int E) {
    int e = blockIdx.x * blockDim.x + threadIdx.x;
    if (e >= E) return;

    int s, d;
    if (g_idx_is64) {
        const long long* p = (const long long*)edge_index;
        s = (int)__ldg(p + e);
        d = (int)__ldg(p + E + e);
    } else {
        const int* p = (const int*)edge_index;
        s = __ldg(p + e);
        d = __ldg(p + E + e);
    }
    float wt = __ldg(w + e);

    unsigned long long rec = (unsigned long long)(unsigned)s
                           | ((unsigned long long)__float_as_uint(wt) << 32);
    int slot = atomicAdd(&g_count[d], 1);
    if (slot < CAP) {
        g_bucket[(size_t)d * CAP + slot] = rec;
    } else {
        // Overflow (expected ~never): append to list, applied post-gather.
        int idx = atomicAdd(&g_ovf_tail, 1);
        if (idx < OVFC) {           // OVFC >= E, so always true; guard anyway
            g_ovf_rec[idx] = rec;
            g_ovf_dst[idx] = d;
        }
    }
}

// ---- 3) gather: 16 threads/node, atomic-free, one STG.128 per lane ----
__global__ __launch_bounds__(TPB)
void gather_kernel(const float* __restrict__ x,
                   float* __restrict__ out,
                   int N) {
    int gid  = blockIdx.x * blockDim.x + threadIdx.x;
    int node = gid >> 4;
    int lane = gid & 15;
    if (node >= N) return;

    int deg = g_count[node];
    if (lane == 0) g_count[node] = 0;   // self-clean for next replay
    if (deg > CAP) deg = CAP;
    const unsigned long long* buf = g_bucket + (size_t)node * CAP;

    float4 a0 = make_float4(0.f, 0.f, 0.f, 0.f);
    float4 a1 = make_float4(0.f, 0.f, 0.f, 0.f);
    float4 a2 = make_float4(0.f, 0.f, 0.f, 0.f);
    float4 a3 = make_float4(0.f, 0.f, 0.f, 0.f);

    int i = 0;
    for (; i + 4 <= deg; i += 4) {
        unsigned long long r0 = buf[i + 0];
        unsigned long long r1 = buf[i + 1];
        unsigned long long r2 = buf[i + 2];
        unsigned long long r3 = buf[i + 3];
        // 4 independent row gathers in flight
        float4 v0 = __ldg(reinterpret_cast<const float4*>(x + (size_t)(unsigned)(r0 & 0xffffffffu) * D) + lane);
        float4 v1 = __ldg(reinterpret_cast<const float4*>(x + (size_t)(unsigned)(r1 & 0xffffffffu) * D) + lane);
        float4 v2 = __ldg(reinterpret_cast<const float4*>(x + (size_t)(unsigned)(r2 & 0xffffffffu) * D) + lane);
        float4 v3 = __ldg(reinterpret_cast<const float4*>(x + (size_t)(unsigned)(r3 & 0xffffffffu) * D) + lane);
        float w0 = __uint_as_float((unsigned)(r0 >> 32));
        float w1 = __uint_as_float((unsigned)(r1 >> 32));
        float w2 = __uint_as_float((unsigned)(r2 >> 32));
        float w3 = __uint_as_float((unsigned)(r3 >> 32));
        a0.x += v0.x * w0; a0.y += v0.y * w0; a0.z += v0.z * w0; a0.w += v0.w * w0;
        a1.x += v1.x * w1; a1.y += v1.y * w1; a1.z += v1.z * w1; a1.w += v1.w * w1;
        a2.x += v2.x * w2; a2.y += v2.y * w2; a2.z += v2.z * w2; a2.w += v2.w * w2;
        a3.x += v3.x * w3; a3.y += v3.y * w3; a3.z += v3.z * w3; a3.w += v3.w * w3;
    }
    for (; i < deg; i++) {
        unsigned long long r = buf[i];
        float4 v = __ldg(reinterpret_cast<const float4*>(x + (size_t)(unsigned)(r & 0xffffffffu) * D) + lane);
        float wt = __uint_as_float((unsigned)(r >> 32));
        a0.x += v.x * wt; a0.y += v.y * wt; a0.z += v.z * wt; a0.w += v.w * wt;
    }

    float4 r;
    r.x = (a0.x + a1.x) + (a2.x + a3.x);
    r.y = (a0.y + a1.y) + (a2.y + a3.y);
    r.z = (a0.z + a1.z) + (a2.z + a3.z);
    r.w = (a0.w + a1.w) + (a2.w + a3.w);

    *(reinterpret_cast<float4*>(out + (size_t)node * D) + lane) = r;
}

// ---- 4) fixup: apply overflow edges (normally zero) + reset tail (1 block) ----
__global__ __launch_bounds__(TPB)
void fixup_kernel(const float* __restrict__ x,
                  float* __restrict__ out) {
    int tail = g_ovf_tail;
    if (tail > OVFC) tail = OVFC;
    for (int e = threadIdx.x; e < tail; e += blockDim.x) {
        unsigned long long rec = g_ovf_rec[e];
        int d = g_ovf_dst[e];
        unsigned s = (unsigned)(rec & 0xffffffffu);
        float wt = __uint_as_float((unsigned)(rec >> 32));
        const float4* xr = reinterpret_cast<const float4*>(x + (size_t)s * D);
        float* orow = out + (size_t)d * D;
        #pragma unroll
        for (int l = 0; l < D / 4; l++) {
            float4 v = __ldg(xr + l);
            float4 m;
            m.x = v.x * wt; m.y = v.y * wt; m.z = v.z * wt; m.w = v.w * wt;
            red_v4(orow + l * 4, m);
        }
    }
    __syncthreads();
    if (threadIdx.x == 0) g_ovf_tail = 0;   // self-clean for next replay
}

extern "C" void kernel_launch(void* const* d_in, const int* in_sizes, int n_in,
                              void* d_out, int out_size) {
    const float* x   = (const float*)d_in[0];
    const void*  ei  = d_in[1];
    const float* w   = (const float*)d_in[2];
    float*       out = (float*)d_out;

    const int E = in_sizes[1] / 2;       // edge_index is (2, E)
    const int N = out_size / D;          // number of nodes

    // 1) dtype probe (counters are zero: module-load init + gather self-clean)
    probe_kernel<<<1, TPB>>>((const int*)ei, E);
    // 2) bucket edges by dst
    {
        int blocks = (E + TPB - 1) / TPB;
        fill_kernel<<<blocks, TPB>>>(ei, w, E);
    }
    // 3) atomic-free gather/accumulate/store (writes every row, resets counters)
    {
        long long total = (long long)N * 16;
        int blocks = (int)((total + TPB - 1) / TPB);
        gather_kernel<<<blocks, TPB>>>(x, out, N);
    }
    // 4) overflow fixup (normally empty) + tail reset
    fixup_kernel<<<1, TPB>>>(x, out);
}

// round 11
// speedup vs baseline: 1.7504x; 1.7504x over previous
#include <cuda_runtime.h>
#include <cstdint>

// out[n,64] = sum over edges e with dst[e]==n of x[src[e],:] * w[e]
// Inputs: x (float32, N*64), edge_index ((2,E), int64-or-int32), edge_weight (float32, E)
//
// Bucketed CSR-lite (R9 skeleton, fixup folded into gather):
//   init  : zero per-node counters + overflow tail, probe index dtype
//   fill  : bucket each edge by dst ({src,w} 8B record); overflow -> list
//   gather: 16 threads/node, atomic-free accumulate, plain STG per row;
//           inline overflow-list scan (tail ~always 0)

static constexpr int D    = 64;       // feature dim
static constexpr int TPB  = 256;
static constexpr int MAXN = 100352;   // >= N (problem: 100000)
static constexpr int CAP  = 32;       // bucket slots/node (P(deg>32) ~ 3e-7/node)
static constexpr int OVFC = 1250000;  // overflow capacity >= E (worst case)

// ---- device scratch (static globals: sanctioned no-alloc scratch) ----
__device__ int g_idx_is64;
__device__ int g_ovf_tail;
__device__ int g_count[MAXN];                                 // per-node counters
__device__ unsigned long long g_bucket[(size_t)MAXN * CAP];   // {src, w} records
__device__ unsigned long long g_ovf_rec[OVFC];                // overflow {src, w}
__device__ int g_ovf_dst[OVFC];                               // overflow dst

// ---- 1) init: zero counters + overflow tail, probe index dtype ----
// int64 indices < 2^31 => every odd 32-bit word is zero; int32 indices are
// random node ids, so all-zero over 1024 samples has probability ~1e-5024.
__global__ void init_kernel(const int* __restrict__ ei32, int E, int N) {
    int i = blockIdx.x * blockDim.x + threadIdx.x;
    if (blockIdx.x == 0) {
        __shared__ int any_nonzero;
        if (threadIdx.x == 0) any_nonzero = 0;
        __syncthreads();
        int n = E < 1024 ? E : 1024;
        for (int k = threadIdx.x; k < n; k += blockDim.x)
            if (ei32[2 * k + 1] != 0) any_nonzero = 1;
        __syncthreads();
        if (threadIdx.x == 0) {
            g_idx_is64 = (any_nonzero == 0) ? 1 : 0;
            g_ovf_tail = 0;
        }
    }
    if (i < N) g_count[i] = 0;
}

// ---- 2) fill: bucket every edge by dst ----
__global__ __launch_bounds__(TPB)
void fill_kernel(const void* __restrict__ edge_index,
                 const float* __restrict__ w,
                 int E) {
    int e = blockIdx.x * blockDim.x + threadIdx.x;
    if (e >= E) return;

    int s, d;
    if (g_idx_is64) {
        const long long* p = (const long long*)edge_index;
        s = (int)__ldg(p + e);
        d = (int)__ldg(p + E + e);
    } else {
        const int* p = (const int*)edge_index;
        s = __ldg(p + e);
        d = __ldg(p + E + e);
    }
    float wt = __ldg(w + e);

    unsigned long long rec = (unsigned long long)(unsigned)s
                           | ((unsigned long long)__float_as_uint(wt) << 32);
    int slot = atomicAdd(&g_count[d], 1);
    if (slot < CAP) {
        g_bucket[(size_t)d * CAP + slot] = rec;
    } else {
        // Overflow (expected ~never): append to list, applied inline in gather.
        int idx = atomicAdd(&g_ovf_tail, 1);
        if (idx < OVFC) {           // OVFC >= E, so always true; guard anyway
            g_ovf_rec[idx] = rec;
            g_ovf_dst[idx] = d;
        }
    }
}

// ---- 3) gather: 16 threads/node, atomic-free, one STG.128 per lane ----
__global__ __launch_bounds__(TPB)
void gather_kernel(const float* __restrict__ x,
                   float* __restrict__ out,
                   int N) {
    int gid  = blockIdx.x * blockDim.x + threadIdx.x;
    int node = gid >> 4;
    int lane = gid & 15;
    if (node >= N) return;

    int deg = g_count[node];
    if (deg > CAP) deg = CAP;
    const unsigned long long* buf = g_bucket + (size_t)node * CAP;

    float4 a0 = make_float4(0.f, 0.f, 0.f, 0.f);
    float4 a1 = make_float4(0.f, 0.f, 0.f, 0.f);
    float4 a2 = make_float4(0.f, 0.f, 0.f, 0.f);
    float4 a3 = make_float4(0.f, 0.f, 0.f, 0.f);

    int i = 0;
    for (; i + 4 <= deg; i += 4) {
        unsigned long long r0 = buf[i + 0];
        unsigned long long r1 = buf[i + 1];
        unsigned long long r2 = buf[i + 2];
        unsigned long long r3 = buf[i + 3];
        // 4 independent row gathers in flight
        float4 v0 = __ldg(reinterpret_cast<const float4*>(x + (size_t)(unsigned)(r0 & 0xffffffffu) * D) + lane);
        float4 v1 = __ldg(reinterpret_cast<const float4*>(x + (size_t)(unsigned)(r1 & 0xffffffffu) * D) + lane);
        float4 v2 = __ldg(reinterpret_cast<const float4*>(x + (size_t)(unsigned)(r2 & 0xffffffffu) * D) + lane);
        float4 v3 = __ldg(reinterpret_cast<const float4*>(x + (size_t)(unsigned)(r3 & 0xffffffffu) * D) + lane);
        float w0 = __uint_as_float((unsigned)(r0 >> 32));
        float w1 = __uint_as_float((unsigned)(r1 >> 32));
        float w2 = __uint_as_float((unsigned)(r2 >> 32));
        float w3 = __uint_as_float((unsigned)(r3 >> 32));
        a0.x += v0.x * w0; a0.y += v0.y * w0; a0.z += v0.z * w0; a0.w += v0.w * w0;
        a1.x += v1.x * w1; a1.y += v1.y * w1; a1.z += v1.z * w1; a1.w += v1.w * w1;
        a2.x += v2.x * w2; a2.y += v2.y * w2; a2.z += v2.z * w2; a2.w += v2.w * w2;
        a3.x += v3.x * w3; a3.y += v3.y * w3; a3.z += v3.z * w3; a3.w += v3.w * w3;
    }
    for (; i < deg; i++) {
        unsigned long long r = buf[i];
        float4 v = __ldg(reinterpret_cast<const float4*>(x + (size_t)(unsigned)(r & 0xffffffffu) * D) + lane);
        float wt = __uint_as_float((unsigned)(r >> 32));
        a0.x += v.x * wt; a0.y += v.y * wt; a0.z += v.z * wt; a0.w += v.w * wt;
    }

    // Inline overflow handling (tail is ~always 0; uniform branch).
    int tail = g_ovf_tail;
    if (tail > 0) {
        if (tail > OVFC) tail = OVFC;
        for (int e = 0; e < tail; e++) {
            if (g_ovf_dst[e] == node) {
                unsigned long long r = g_ovf_rec[e];
                float4 v = __ldg(reinterpret_cast<const float4*>(
                    x + (size_t)(unsigned)(r & 0xffffffffu) * D) + lane);
                float wt = __uint_as_float((unsigned)(r >> 32));
                a0.x += v.x * wt; a0.y += v.y * wt;
                a0.z += v.z * wt; a0.w += v.w * wt;
            }
        }
    }

    float4 r;
    r.x = (a0.x + a1.x) + (a2.x + a3.x);
    r.y = (a0.y + a1.y) + (a2.y + a3.y);
    r.z = (a0.z + a1.z) + (a2.z + a3.z);
    r.w = (a0.w + a1.w) + (a2.w + a3.w);

    *(reinterpret_cast<float4*>(out + (size_t)node * D) + lane) = r;
}

extern "C" void kernel_launch(void* const* d_in, const int* in_sizes, int n_in,
                              void* d_out, int out_size) {
    const float* x   = (const float*)d_in[0];
    const void*  ei  = d_in[1];
    const float* w   = (const float*)d_in[2];
    float*       out = (float*)d_out;

    const int E = in_sizes[1] / 2;       // edge_index is (2, E)
    const int N = out_size / D;          // number of nodes

    // 1) init: zero counters + tail, probe dtype
    {
        int blocks = (N + TPB - 1) / TPB;
        init_kernel<<<blocks, TPB>>>((const int*)ei, E, N);
    }
    // 2) bucket edges by dst
    {
        int blocks = (E + TPB - 1) / TPB;
        fill_kernel<<<blocks, TPB>>>(ei, w, E);
    }
    // 3) atomic-free gather/accumulate/store (handles overflow inline)
    {
        long long total = (long long)N * 16;
        int blocks = (int)((total + TPB - 1) / TPB);
        gather_kernel<<<blocks, TPB>>>(x, out, N);
    }
}